// round 15
// baseline (speedup 1.0000x reference)
#include <cuda_runtime.h>
#include <cuda_bf16.h>
#include <stdint.h>

// ---------------------------------------------------------------------------
// ShallowGCNet: 4x GCNConv(lrelu) + dropout + dense
// N=50000, E=800000, features 256->256->256->128->64->10
// GEMM: bf16 double-split (3 products) m16n8k16 mma.sync + ldmatrix,
// cp.async 2-stage pipeline, 2 CTAs/SM. Aggregation: CSR gather (L2-bound).
// CSR build forked to a side stream; gather->GEMM boundaries chunk-pipelined
// across two streams with double-buffered tmp (tA/tB).
// ---------------------------------------------------------------------------

__device__ float g_tmpA[50000 * 256];
__device__ float g_tmpB[50000 * 256];
__device__ __nv_bfloat16 g_ah[50000 * 256];  // A hi plane
__device__ __nv_bfloat16 g_al[50000 * 256];  // A lo plane
__device__ __nv_bfloat16 g_wh[172032];       // W^T hi  [Fout][K]
__device__ __nv_bfloat16 g_wl[172032];       // W^T lo
// offsets: w1=0 w2=65536 w3=131072 w4=163840
__device__ float g_dinv[50000];
__device__ int   g_deg[50000];
__device__ int   g_off[50001];
__device__ int   g_bsum[64];
__device__ int   g_fill[50000];
__device__ int   g_csr_src[800000];
__device__ float g_csr_w[800000];

// ------------------------------ degree ------------------------------------
__global__ void deg_init_kernel(int n) {
  int i = blockIdx.x * blockDim.x + threadIdx.x;
  if (i < n) { g_deg[i] = 0; g_fill[i] = 0; }
}
__global__ void deg_count_kernel(const int* __restrict__ dst, int E) {
  int e = blockIdx.x * blockDim.x + threadIdx.x;
  if (e < E) atomicAdd(&g_deg[dst[e]], 1);
}

// ------------------------------ CSR build ----------------------------------
#define SCAN_BLK 1024
__global__ void scan1_kernel(int n) {   // also computes dinv
  __shared__ int sh[SCAN_BLK];
  int i = blockIdx.x * SCAN_BLK + threadIdx.x;
  int v = (i < n) ? g_deg[i] : 0;
  if (i < n) g_dinv[i] = 1.0f / sqrtf((float)(v + 1));  // +1 self-loop
  sh[threadIdx.x] = v;
  __syncthreads();
#pragma unroll
  for (int d = 1; d < SCAN_BLK; d <<= 1) {
    int t = (threadIdx.x >= d) ? sh[threadIdx.x - d] : 0;
    __syncthreads();
    sh[threadIdx.x] += t;
    __syncthreads();
  }
  if (i < n) g_off[i] = sh[threadIdx.x] - v;
  if (threadIdx.x == SCAN_BLK - 1) g_bsum[blockIdx.x] = sh[threadIdx.x];
}
__global__ void scan2_kernel(int nb) {
  __shared__ int sh[64];
  int v = (threadIdx.x < nb) ? g_bsum[threadIdx.x] : 0;
  sh[threadIdx.x] = v;
  __syncthreads();
#pragma unroll
  for (int d = 1; d < 64; d <<= 1) {
    int t = (threadIdx.x >= d) ? sh[threadIdx.x - d] : 0;
    __syncthreads();
    sh[threadIdx.x] += t;
    __syncthreads();
  }
  if (threadIdx.x < nb) g_bsum[threadIdx.x] = sh[threadIdx.x] - v;
}
__global__ void scan3_kernel(int n, int E) {
  int i = blockIdx.x * blockDim.x + threadIdx.x;
  if (i < n) g_off[i] += g_bsum[i >> 10];
  if (i == n) g_off[n] = E;
}
__global__ void fill_kernel(const int* __restrict__ src,
                            const int* __restrict__ dst, int E) {
  int e = blockIdx.x * blockDim.x + threadIdx.x;
  if (e >= E) return;
  int s = src[e], d = dst[e];
  int pos = g_off[d] + atomicAdd(&g_fill[d], 1);
  g_csr_src[pos] = s;
  g_csr_w[pos] = g_dinv[s];
}

// ------------------------- bf16 split helpers -------------------------------
__device__ __forceinline__ uint32_t pack_bf2(__nv_bfloat16 a, __nv_bfloat16 b) {
  return (uint32_t)__bfloat16_as_ushort(a) |
         ((uint32_t)__bfloat16_as_ushort(b) << 16);
}

__global__ void split_x_kernel(const float* __restrict__ x,
                               __nv_bfloat16* __restrict__ h,
                               __nv_bfloat16* __restrict__ l, int n) {
  int i = blockIdx.x * blockDim.x + threadIdx.x;
  if (i >= n) return;
  float v = x[i];
  __nv_bfloat16 hh = __float2bfloat16(v);
  h[i] = hh;
  l[i] = __float2bfloat16(v - __bfloat162float(hh));
}

__global__ void split_wt_all_kernel(const float* __restrict__ W1,
                                    const float* __restrict__ W2,
                                    const float* __restrict__ W3,
                                    const float* __restrict__ W4,
                                    __nv_bfloat16* __restrict__ h,
                                    __nv_bfloat16* __restrict__ l) {
  int i = blockIdx.x * blockDim.x + threadIdx.x;
  if (i >= 172032) return;
  const float* W; int K, F, base, i0;
  if (i < 65536)        { W = W1; K = 256; F = 256; base = 0;      i0 = i; }
  else if (i < 131072)  { W = W2; K = 256; F = 256; base = 65536;  i0 = i - 65536; }
  else if (i < 163840)  { W = W3; K = 256; F = 128; base = 131072; i0 = i - 131072; }
  else                  { W = W4; K = 128; F = 64;  base = 163840; i0 = i - 163840; }
  int k = i0 / F, nn = i0 % F;
  float v = W[i0];
  __nv_bfloat16 hh = __float2bfloat16(v);
  h[base + nn * K + k] = hh;
  l[base + nn * K + k] = __float2bfloat16(v - __bfloat162float(hh));
}

// ------------------------ bf16 mma GEMM ------------------------------------
__device__ __forceinline__ void cp16(uint32_t dst, const void* src) {
  asm volatile("cp.async.ca.shared.global [%0], [%1], 16;"
               :: "r"(dst), "l"(src));
}
__device__ __forceinline__ void cp_commit() {
  asm volatile("cp.async.commit_group;");
}
template<int n> __device__ __forceinline__ void cp_wait() {
  asm volatile("cp.async.wait_group %0;" :: "n"(n));
}

#define MMA_BF16(c, a, b0, b1)                                         \
  asm volatile(                                                        \
      "mma.sync.aligned.m16n8k16.row.col.f32.bf16.bf16.f32 "           \
      "{%0,%1,%2,%3}, {%4,%5,%6,%7}, {%8,%9}, {%0,%1,%2,%3};"          \
      : "+f"((c)[0]), "+f"((c)[1]), "+f"((c)[2]), "+f"((c)[3])         \
      : "r"((a)[0]), "r"((a)[1]), "r"((a)[2]), "r"((a)[3]),            \
        "r"(b0), "r"(b1))

#define LDM4(r, addr)                                                  \
  asm volatile("ldmatrix.sync.aligned.m8n8.x4.shared.b16 "             \
               "{%0,%1,%2,%3}, [%4];"                                  \
               : "=r"((r)[0]), "=r"((r)[1]), "=r"((r)[2]), "=r"((r)[3])\
               : "r"(addr))

// rowbase: M-chunk offset (chunk pipelining). Each block covers rows
// [rowbase + bx*128, rowbase + bx*128 + 128); clamp stays inside own chunk.
template<int BN>
__global__ void __launch_bounds__(256, 2) gemm_bf16_kernel(
    const __nv_bfloat16* __restrict__ Ah, const __nv_bfloat16* __restrict__ Al,
    const __nv_bfloat16* __restrict__ Bh, const __nv_bfloat16* __restrict__ Bl,
    float* __restrict__ C, int rowbase, int N, int K, int Fout) {
  constexpr int SB = BN * 80;
  constexpr int ST = 20480 + 2 * SB;
  constexpr int NA = BN / 16;
  constexpr int NP = NA / 2;
  extern __shared__ char smc[];
  const uint32_t smu = (uint32_t)__cvta_generic_to_shared(smc);

  const int tid = threadIdx.x;
  const int wid = tid >> 5, lane = tid & 31;
  const int wm = wid & 3, wn = wid >> 2;
  const int row0 = rowbase + blockIdx.x * 128;
  const int col0 = blockIdx.y * BN;
  const int NIT = K >> 5;

  const uint32_t a_rel =
      (uint32_t)(wm * 32 + (lane & 15)) * 80u + (uint32_t)(lane >> 4) * 16u;
  const uint32_t b_rel = 20480u +
      (uint32_t)(wn * (BN / 2) + (lane & 7) + ((lane >> 4) << 3)) * 80u +
      (uint32_t)((lane >> 3) & 1) * 16u;

  float c[2][NA][4] = {};

  auto load_stage = [&](int s, int k0) {
    uint32_t sb = smu + (uint32_t)s * ST;
    int r = tid >> 2, q = tid & 3;
#pragma unroll
    for (int p = 0; p < 2; ++p) {
      int rr = r + p * 64;
      int grow = row0 + rr; if (grow >= N) grow = N - 1;
      cp16(sb + rr * 80 + q * 16, Ah + (size_t)grow * K + k0 + q * 8);
      cp16(sb + 10240 + rr * 80 + q * 16, Al + (size_t)grow * K + k0 + q * 8);
    }
#pragma unroll
    for (int p = 0; p < BN / 64; ++p) {
      int rr = r + p * 64;
      int gc = col0 + rr;
      cp16(sb + 20480 + rr * 80 + q * 16, Bh + (size_t)gc * K + k0 + q * 8);
      cp16(sb + 20480 + SB + rr * 80 + q * 16, Bl + (size_t)gc * K + k0 + q * 8);
    }
  };

  load_stage(0, 0);
  cp_commit();
  for (int it = 0; it < NIT; ++it) {
    if (it + 1 < NIT) {
      load_stage((it + 1) & 1, (it + 1) * 32);
      cp_commit();
      cp_wait<1>();
    } else {
      cp_wait<0>();
    }
    __syncthreads();
    uint32_t sbu = smu + (uint32_t)(it & 1) * ST;
#pragma unroll
    for (int ka = 0; ka < 2; ++ka) {
      uint32_t ah[2][4], al[2][4];
#pragma unroll
      for (int ma = 0; ma < 2; ++ma) {
        uint32_t base = sbu + a_rel + (uint32_t)ma * 1280u + (uint32_t)ka * 32u;
        LDM4(ah[ma], base);
        LDM4(al[ma], base + 10240u);
      }
#pragma unroll
      for (int p = 0; p < NP; ++p) {
        uint32_t base = sbu + b_rel + (uint32_t)p * (16u * 80u) + (uint32_t)ka * 32u;
        uint32_t rb[4], rl[4];
        LDM4(rb, base);
        LDM4(rl, base + (uint32_t)SB);
#pragma unroll
        for (int ma = 0; ma < 2; ++ma) {
          MMA_BF16(c[ma][2 * p],     ah[ma], rb[0], rb[1]);
          MMA_BF16(c[ma][2 * p],     al[ma], rb[0], rb[1]);
          MMA_BF16(c[ma][2 * p],     ah[ma], rl[0], rl[1]);
          MMA_BF16(c[ma][2 * p + 1], ah[ma], rb[2], rb[3]);
          MMA_BF16(c[ma][2 * p + 1], al[ma], rb[2], rb[3]);
          MMA_BF16(c[ma][2 * p + 1], ah[ma], rl[2], rl[3]);
        }
      }
    }
    __syncthreads();
  }

  const int gq = lane >> 2, tq = lane & 3;
#pragma unroll
  for (int ma = 0; ma < 2; ++ma) {
    int row = row0 + wm * 32 + ma * 16 + gq;
#pragma unroll
    for (int na = 0; na < NA; ++na) {
      int col = col0 + wn * (BN / 2) + na * 8 + tq * 2;
      if (row < N)
        *(float2*)(C + (size_t)row * Fout + col) =
            make_float2(c[ma][na][0], c[ma][na][1]);
      if (row + 8 < N)
        *(float2*)(C + (size_t)(row + 8) * Fout + col) =
            make_float2(c[ma][na][2], c[ma][na][3]);
    }
  }
}

// -------------- CSR gather + fused bias/lrelu/bf16-split --------------------
// Processes dst rows [w0, wend).
template<int F>
__global__ void gather_split_kernel(const float* __restrict__ tmp,
                                    const float* __restrict__ bias,
                                    __nv_bfloat16* __restrict__ oh,
                                    __nv_bfloat16* __restrict__ ol,
                                    int w0, int wend) {
  int w = w0 + ((blockIdx.x * blockDim.x + threadIdx.x) >> 5);
  int lane = threadIdx.x & 31;
  if (w >= wend) return;
  int beg = g_off[w], end = g_off[w + 1];
  float dr = g_dinv[w];
  constexpr int NV = F / 128;
  float4 acc[NV];
  const float4* self = (const float4*)(tmp + (size_t)w * F);
#pragma unroll
  for (int v = 0; v < NV; ++v) {
    float4 x = self[lane + 32 * v];
    acc[v] = make_float4(x.x * dr, x.y * dr, x.z * dr, x.w * dr);
  }
  for (int e0 = beg; e0 < end; e0 += 32) {
    int ne = min(32, end - e0);
    int s = 0; float ww = 0.f;
    if (lane < ne) { s = g_csr_src[e0 + lane]; ww = g_csr_w[e0 + lane]; }
    for (int j = 0; j < ne; ++j) {
      int sj = __shfl_sync(0xffffffffu, s, j);
      float wj = __shfl_sync(0xffffffffu, ww, j);
      const float4* sr = (const float4*)(tmp + (size_t)sj * F);
#pragma unroll
      for (int v = 0; v < NV; ++v) {
        float4 x = sr[lane + 32 * v];
        acc[v].x += wj * x.x; acc[v].y += wj * x.y;
        acc[v].z += wj * x.z; acc[v].w += wj * x.w;
      }
    }
  }
  uint32_t* ph = (uint32_t*)(oh + (size_t)w * F);
  uint32_t* pl = (uint32_t*)(ol + (size_t)w * F);
#pragma unroll
  for (int v = 0; v < NV; ++v) {
    int cb = lane + 32 * v;
    float4 b = *(const float4*)(bias + 4 * cb);
    float4 z = make_float4(acc[v].x * dr + b.x, acc[v].y * dr + b.y,
                           acc[v].z * dr + b.z, acc[v].w * dr + b.w);
    z.x = z.x > 0.f ? z.x : 0.01f * z.x;
    z.y = z.y > 0.f ? z.y : 0.01f * z.y;
    z.z = z.z > 0.f ? z.z : 0.01f * z.z;
    z.w = z.w > 0.f ? z.w : 0.01f * z.w;
    __nv_bfloat16 hx = __float2bfloat16(z.x), hy = __float2bfloat16(z.y);
    __nv_bfloat16 hz = __float2bfloat16(z.z), hw = __float2bfloat16(z.w);
    ph[2 * cb + 0] = pack_bf2(hx, hy);
    ph[2 * cb + 1] = pack_bf2(hz, hw);
    pl[2 * cb + 0] = pack_bf2(__float2bfloat16(z.x - __bfloat162float(hx)),
                              __float2bfloat16(z.y - __bfloat162float(hy)));
    pl[2 * cb + 1] = pack_bf2(__float2bfloat16(z.z - __bfloat162float(hz)),
                              __float2bfloat16(z.w - __bfloat162float(hw)));
  }
}

// ------------------- dropout (JAX threefry) -------------------------
#define TF_ROUND(x0, x1, r)                         \
  { x0 += x1; x1 = (x1 << (r)) | (x1 >> (32 - (r))); x1 ^= x0; }

__device__ __forceinline__ uint32_t threefry_bits(uint32_t idx) {
  const uint32_t k0 = 0u, k1 = 42u;
  const uint32_t k2 = 0x1BD11BDAu ^ k0 ^ k1;
  uint32_t x0 = 0u, x1 = idx;
  x0 += k0; x1 += k1;
  TF_ROUND(x0, x1, 13) TF_ROUND(x0, x1, 15) TF_ROUND(x0, x1, 26) TF_ROUND(x0, x1, 6)
  x0 += k1; x1 += k2 + 1u;
  TF_ROUND(x0, x1, 17) TF_ROUND(x0, x1, 29) TF_ROUND(x0, x1, 16) TF_ROUND(x0, x1, 24)
  x0 += k2; x1 += k0 + 2u;
  TF_ROUND(x0, x1, 13) TF_ROUND(x0, x1, 15) TF_ROUND(x0, x1, 26) TF_ROUND(x0, x1, 6)
  x0 += k0; x1 += k1 + 3u;
  TF_ROUND(x0, x1, 17) TF_ROUND(x0, x1, 29) TF_ROUND(x0, x1, 16) TF_ROUND(x0, x1, 24)
  x0 += k1; x1 += k2 + 4u;
  TF_ROUND(x0, x1, 13) TF_ROUND(x0, x1, 15) TF_ROUND(x0, x1, 26) TF_ROUND(x0, x1, 6)
  x0 += k2; x1 += k0 + 5u;
  return x0 ^ x1;
}

// L4 gather fused with bias4 + lrelu + dropout + dense 64->10.
__global__ void gather_final_kernel(const float* __restrict__ tmp,
                                    const float* __restrict__ b4,
                                    const float* __restrict__ W5,
                                    const float* __restrict__ b5,
                                    float* __restrict__ out, int n) {
  __shared__ float w5s[640];
  __shared__ float b5s[16];
  for (int i = threadIdx.x; i < 640; i += blockDim.x) w5s[i] = W5[i];
  if (threadIdx.x < 10) b5s[threadIdx.x] = b5[threadIdx.x];
  __syncthreads();

  int w = (blockIdx.x * blockDim.x + threadIdx.x) >> 5;
  int lane = threadIdx.x & 31;
  if (w >= n) return;
  int beg = g_off[w], end = g_off[w + 1];
  float dr = g_dinv[w];
  float2 acc;
  {
    float2 x = ((const float2*)(tmp + (size_t)w * 64))[lane];
    acc = make_float2(x.x * dr, x.y * dr);
  }
  for (int e0 = beg; e0 < end; e0 += 32) {
    int ne = min(32, end - e0);
    int s = 0; float ww = 0.f;
    if (lane < ne) { s = g_csr_src[e0 + lane]; ww = g_csr_w[e0 + lane]; }
    for (int j = 0; j < ne; ++j) {
      int sj = __shfl_sync(0xffffffffu, s, j);
      float wj = __shfl_sync(0xffffffffu, ww, j);
      float2 x = ((const float2*)(tmp + (size_t)sj * 64))[lane];
      acc.x += wj * x.x; acc.y += wj * x.y;
    }
  }
  int f0 = 2 * lane, f1 = 2 * lane + 1;
  float v0 = acc.x * dr + b4[f0];
  v0 = (v0 > 0.f) ? v0 : 0.01f * v0;
  float v1 = acc.y * dr + b4[f1];
  v1 = (v1 > 0.f) ? v1 : 0.01f * v1;
  uint32_t bits0 = threefry_bits((uint32_t)(w * 64 + f0));
  uint32_t bits1 = threefry_bits((uint32_t)(w * 64 + f1));
  v0 = (bits0 & 0x80000000u) ? 0.f : v0 * 2.f;
  v1 = (bits1 & 0x80000000u) ? 0.f : v1 * 2.f;
#pragma unroll
  for (int j = 0; j < 10; ++j) {
    float p = v0 * w5s[f0 * 10 + j] + v1 * w5s[f1 * 10 + j];
#pragma unroll
    for (int off = 16; off; off >>= 1)
      p += __shfl_xor_sync(0xffffffffu, p, off);
    if (lane == 0) out[w * 10 + j] = p + b5s[j];
  }
}

// ------------------------------ launch -------------------------------------
extern "C" void kernel_launch(void* const* d_in, const int* in_sizes, int n_in,
                              void* d_out, int out_size) {
  const float* x = (const float*)d_in[0];
  const int* ei = (const int*)d_in[1];   // int32
  const float* W1 = (const float*)d_in[2];
  const float* b1 = (const float*)d_in[3];
  const float* W2 = (const float*)d_in[4];
  const float* b2 = (const float*)d_in[5];
  const float* W3 = (const float*)d_in[6];
  const float* b3 = (const float*)d_in[7];
  const float* W4 = (const float*)d_in[8];
  const float* b4 = (const float*)d_in[9];
  const float* W5 = (const float*)d_in[10];
  const float* b5 = (const float*)d_in[11];
  const int N = in_sizes[0] / 256;
  const int E = in_sizes[1] / 2;
  const int* src = ei;
  const int* dstp = ei + E;

  float* tA = nullptr; float* tB = nullptr;
  __nv_bfloat16 *ah = nullptr, *al = nullptr, *wh = nullptr, *wl = nullptr;
  cudaGetSymbolAddress((void**)&tA, g_tmpA);
  cudaGetSymbolAddress((void**)&tB, g_tmpB);
  cudaGetSymbolAddress((void**)&ah, g_ah);
  cudaGetSymbolAddress((void**)&al, g_al);
  cudaGetSymbolAddress((void**)&wh, g_wh);
  cudaGetSymbolAddress((void**)&wl, g_wl);

  constexpr int SM_128 = 2 * (20480 + 2 * 128 * 80);  // 81920
  constexpr int SM_64  = 2 * (20480 + 2 * 64 * 80);   // 61440
  cudaFuncSetAttribute(gemm_bf16_kernel<128>,
                       cudaFuncAttributeMaxDynamicSharedMemorySize, SM_128);
  cudaFuncSetAttribute(gemm_bf16_kernel<64>,
                       cudaFuncAttributeMaxDynamicSharedMemorySize, SM_64);

  // Streams/events created once on the first (non-captured) call.
  static cudaStream_t s2 = nullptr;
  static cudaEvent_t ev_fork = nullptr, ev_join = nullptr;
  static cudaEvent_t eg[3] = {nullptr, nullptr, nullptr};   // gather_c0 done
  static cudaEvent_t fg[3] = {nullptr, nullptr, nullptr};   // GEMM_c0 done
  if (s2 == nullptr) {
    cudaStreamCreateWithFlags(&s2, cudaStreamNonBlocking);
    cudaEventCreateWithFlags(&ev_fork, cudaEventDisableTiming);
    cudaEventCreateWithFlags(&ev_join, cudaEventDisableTiming);
    for (int i = 0; i < 3; ++i) {
      cudaEventCreateWithFlags(&eg[i], cudaEventDisableTiming);
      cudaEventCreateWithFlags(&fg[i], cudaEventDisableTiming);
    }
  }

  // chunk geometry (row-aligned to 128)
  const int MB = (N + 127) / 128;            // 391
  const int C0 = ((N / 2 + 127) / 128) * 128;  // 25088
  const int NB0 = C0 / 128;                  // 196
  const int NB1 = (N - C0 + 127) / 128;      // 195
  const int GW0 = (C0 * 32 + 255) / 256;
  const int GW1 = ((N - C0) * 32 + 255) / 256;
  const int GW = (N * 32 + 255) / 256;

  // ---- fork: CSR build on s2, overlapped with splits + L1 GEMM ----
  cudaEventRecord(ev_fork, 0);
  cudaStreamWaitEvent(s2, ev_fork, 0);
  deg_init_kernel<<<(N + 255) / 256, 256, 0, s2>>>(N);
  deg_count_kernel<<<(E + 255) / 256, 256, 0, s2>>>(dstp, E);
  int nblk = (N + SCAN_BLK - 1) / SCAN_BLK;
  scan1_kernel<<<nblk, SCAN_BLK, 0, s2>>>(N);
  scan2_kernel<<<1, 64, 0, s2>>>(nblk);
  scan3_kernel<<<(N + 256) / 256, 256, 0, s2>>>(N, E);
  fill_kernel<<<(E + 255) / 256, 256, 0, s2>>>(src, dstp, E);
  cudaEventRecord(ev_join, s2);

  // ---- main: splits + L1 GEMM (full; g1 needs all of tA) ----
  split_x_kernel<<<(N * 256 + 255) / 256, 256>>>(x, ah, al, N * 256);
  split_wt_all_kernel<<<(172032 + 255) / 256, 256>>>(W1, W2, W3, W4, wh, wl);
  gemm_bf16_kernel<128><<<dim3(MB, 2), 256, SM_128>>>(
      ah, al, wh, wl, tA, 0, N, 256, 256);
  cudaStreamWaitEvent(0, ev_join, 0);   // gathers need the CSR

  // ===== boundary 1: gather1(tA) chunked || GEMM2(->tB) chunked =====
  gather_split_kernel<256><<<GW0, 256>>>(tA, b1, ah, al, 0, C0);
  cudaEventRecord(eg[0], 0);
  gather_split_kernel<256><<<GW1, 256>>>(tA, b1, ah, al, C0, N);
  cudaStreamWaitEvent(s2, eg[0], 0);
  gemm_bf16_kernel<128><<<dim3(NB0, 2), 256, SM_128, s2>>>(
      ah, al, wh + 65536, wl + 65536, tB, 0, N, 256, 256);
  cudaEventRecord(fg[0], s2);
  gemm_bf16_kernel<128><<<dim3(NB1, 2), 256, SM_128>>>(
      ah, al, wh + 65536, wl + 65536, tB, C0, N, 256, 256);

  // ===== boundary 2: gather2(tB) chunked || GEMM3(->tA) chunked =====
  cudaStreamWaitEvent(0, fg[0], 0);
  gather_split_kernel<256><<<GW0, 256>>>(tB, b2, ah, al, 0, C0);
  cudaEventRecord(eg[1], 0);
  gather_split_kernel<256><<<GW1, 256>>>(tB, b2, ah, al, C0, N);
  cudaStreamWaitEvent(s2, eg[1], 0);
  gemm_bf16_kernel<128><<<dim3(NB0, 1), 256, SM_128, s2>>>(
      ah, al, wh + 131072, wl + 131072, tA, 0, N, 256, 128);
  cudaEventRecord(fg[1], s2);
  gemm_bf16_kernel<128><<<dim3(NB1, 1), 256, SM_128>>>(
      ah, al, wh + 131072, wl + 131072, tA, C0, N, 256, 128);

  // ===== boundary 3: gather3(tA,F=128) chunked || GEMM4(->tB) chunked =====
  cudaStreamWaitEvent(0, fg[1], 0);
  gather_split_kernel<128><<<GW0, 256>>>(tA, b3, ah, al, 0, C0);
  cudaEventRecord(eg[2], 0);
  gather_split_kernel<128><<<GW1, 256>>>(tA, b3, ah, al, C0, N);
  cudaStreamWaitEvent(s2, eg[2], 0);
  gemm_bf16_kernel<64><<<dim3(NB0, 1), 256, SM_64, s2>>>(
      ah, al, wh + 163840, wl + 163840, tB, 0, N, 128, 64);
  cudaEventRecord(fg[2], s2);
  gemm_bf16_kernel<64><<<dim3(NB1, 1), 256, SM_64>>>(
      ah, al, wh + 163840, wl + 163840, tB, C0, N, 128, 64);

  // ===== final: gather(tB) + bias + lrelu + dropout + dense =====
  cudaStreamWaitEvent(0, fg[2], 0);
  gather_final_kernel<<<GW, 256>>>(tB, b4, W5, b5, (float*)d_out, N);
}

// round 16
// speedup vs baseline: 1.0185x; 1.0185x over previous
#include <cuda_runtime.h>
#include <cuda_bf16.h>
#include <stdint.h>

// ---------------------------------------------------------------------------
// ShallowGCNet: 4x GCNConv(lrelu) + dropout + dense
// N=50000, E=800000, features 256->256->256->128->64->10
// GEMM: bf16 double-split (3 products) m16n8k16 mma.sync + ldmatrix,
// cp.async 2-stage pipeline, 2 CTAs/SM. Aggregation: CSR gather (L2-bound).
// Side stream: W-split + CSR build, overlapped with split_x + L1 GEMM.
// (R15 chunk pipelining reverted: gather saturates LTS; concurrent GEMM
//  L2 traffic + wave tails made it a net regression.)
// ---------------------------------------------------------------------------

__device__ float g_tmp[50000 * 256];   // GEMM output / gather input
__device__ __nv_bfloat16 g_ah[50000 * 256];  // A hi plane
__device__ __nv_bfloat16 g_al[50000 * 256];  // A lo plane
__device__ __nv_bfloat16 g_wh[172032];       // W^T hi  [Fout][K]
__device__ __nv_bfloat16 g_wl[172032];       // W^T lo
// offsets: w1=0 w2=65536 w3=131072 w4=163840
__device__ float g_dinv[50000];
__device__ int   g_deg[50000];
__device__ int   g_off[50001];
__device__ int   g_bsum[64];
__device__ int   g_fill[50000];
__device__ int   g_csr_src[800000];
__device__ float g_csr_w[800000];

// ------------------------------ degree ------------------------------------
__global__ void deg_init_kernel(int n) {
  int i = blockIdx.x * blockDim.x + threadIdx.x;
  if (i < n) { g_deg[i] = 0; g_fill[i] = 0; }
}
__global__ void deg_count_kernel(const int* __restrict__ dst, int E) {
  int e = blockIdx.x * blockDim.x + threadIdx.x;
  if (e < E) atomicAdd(&g_deg[dst[e]], 1);
}

// ------------------------------ CSR build ----------------------------------
#define SCAN_BLK 1024
__global__ void scan1_kernel(int n) {   // also computes dinv
  __shared__ int sh[SCAN_BLK];
  int i = blockIdx.x * SCAN_BLK + threadIdx.x;
  int v = (i < n) ? g_deg[i] : 0;
  if (i < n) g_dinv[i] = 1.0f / sqrtf((float)(v + 1));  // +1 self-loop
  sh[threadIdx.x] = v;
  __syncthreads();
#pragma unroll
  for (int d = 1; d < SCAN_BLK; d <<= 1) {
    int t = (threadIdx.x >= d) ? sh[threadIdx.x - d] : 0;
    __syncthreads();
    sh[threadIdx.x] += t;
    __syncthreads();
  }
  if (i < n) g_off[i] = sh[threadIdx.x] - v;
  if (threadIdx.x == SCAN_BLK - 1) g_bsum[blockIdx.x] = sh[threadIdx.x];
}
__global__ void scan2_kernel(int nb) {
  __shared__ int sh[64];
  int v = (threadIdx.x < nb) ? g_bsum[threadIdx.x] : 0;
  sh[threadIdx.x] = v;
  __syncthreads();
#pragma unroll
  for (int d = 1; d < 64; d <<= 1) {
    int t = (threadIdx.x >= d) ? sh[threadIdx.x - d] : 0;
    __syncthreads();
    sh[threadIdx.x] += t;
    __syncthreads();
  }
  if (threadIdx.x < nb) g_bsum[threadIdx.x] = sh[threadIdx.x] - v;
}
__global__ void scan3_kernel(int n, int E) {
  int i = blockIdx.x * blockDim.x + threadIdx.x;
  if (i < n) g_off[i] += g_bsum[i >> 10];
  if (i == n) g_off[n] = E;
}
__global__ void fill_kernel(const int* __restrict__ src,
                            const int* __restrict__ dst, int E) {
  int e = blockIdx.x * blockDim.x + threadIdx.x;
  if (e >= E) return;
  int s = src[e], d = dst[e];
  int pos = g_off[d] + atomicAdd(&g_fill[d], 1);
  g_csr_src[pos] = s;
  g_csr_w[pos] = g_dinv[s];
}

// ------------------------- bf16 split helpers -------------------------------
__device__ __forceinline__ uint32_t pack_bf2(__nv_bfloat16 a, __nv_bfloat16 b) {
  return (uint32_t)__bfloat16_as_ushort(a) |
         ((uint32_t)__bfloat16_as_ushort(b) << 16);
}

__global__ void split_x_kernel(const float* __restrict__ x,
                               __nv_bfloat16* __restrict__ h,
                               __nv_bfloat16* __restrict__ l, int n) {
  int i = blockIdx.x * blockDim.x + threadIdx.x;
  if (i >= n) return;
  float v = x[i];
  __nv_bfloat16 hh = __float2bfloat16(v);
  h[i] = hh;
  l[i] = __float2bfloat16(v - __bfloat162float(hh));
}

__global__ void split_wt_all_kernel(const float* __restrict__ W1,
                                    const float* __restrict__ W2,
                                    const float* __restrict__ W3,
                                    const float* __restrict__ W4,
                                    __nv_bfloat16* __restrict__ h,
                                    __nv_bfloat16* __restrict__ l) {
  int i = blockIdx.x * blockDim.x + threadIdx.x;
  if (i >= 172032) return;
  const float* W; int K, F, base, i0;
  if (i < 65536)        { W = W1; K = 256; F = 256; base = 0;      i0 = i; }
  else if (i < 131072)  { W = W2; K = 256; F = 256; base = 65536;  i0 = i - 65536; }
  else if (i < 163840)  { W = W3; K = 256; F = 128; base = 131072; i0 = i - 131072; }
  else                  { W = W4; K = 128; F = 64;  base = 163840; i0 = i - 163840; }
  int k = i0 / F, nn = i0 % F;
  float v = W[i0];
  __nv_bfloat16 hh = __float2bfloat16(v);
  h[base + nn * K + k] = hh;
  l[base + nn * K + k] = __float2bfloat16(v - __bfloat162float(hh));
}

// ------------------------ bf16 mma GEMM ------------------------------------
__device__ __forceinline__ void cp16(uint32_t dst, const void* src) {
  asm volatile("cp.async.ca.shared.global [%0], [%1], 16;"
               :: "r"(dst), "l"(src));
}
__device__ __forceinline__ void cp_commit() {
  asm volatile("cp.async.commit_group;");
}
template<int n> __device__ __forceinline__ void cp_wait() {
  asm volatile("cp.async.wait_group %0;" :: "n"(n));
}

#define MMA_BF16(c, a, b0, b1)                                         \
  asm volatile(                                                        \
      "mma.sync.aligned.m16n8k16.row.col.f32.bf16.bf16.f32 "           \
      "{%0,%1,%2,%3}, {%4,%5,%6,%7}, {%8,%9}, {%0,%1,%2,%3};"          \
      : "+f"((c)[0]), "+f"((c)[1]), "+f"((c)[2]), "+f"((c)[3])         \
      : "r"((a)[0]), "r"((a)[1]), "r"((a)[2]), "r"((a)[3]),            \
        "r"(b0), "r"(b1))

#define LDM4(r, addr)                                                  \
  asm volatile("ldmatrix.sync.aligned.m8n8.x4.shared.b16 "             \
               "{%0,%1,%2,%3}, [%4];"                                  \
               : "=r"((r)[0]), "=r"((r)[1]), "=r"((r)[2]), "=r"((r)[3])\
               : "r"(addr))

template<int BN>
__global__ void __launch_bounds__(256, 2) gemm_bf16_kernel(
    const __nv_bfloat16* __restrict__ Ah, const __nv_bfloat16* __restrict__ Al,
    const __nv_bfloat16* __restrict__ Bh, const __nv_bfloat16* __restrict__ Bl,
    float* __restrict__ C, int N, int K, int Fout) {
  constexpr int SB = BN * 80;
  constexpr int ST = 20480 + 2 * SB;
  constexpr int NA = BN / 16;
  constexpr int NP = NA / 2;
  extern __shared__ char smc[];
  const uint32_t smu = (uint32_t)__cvta_generic_to_shared(smc);

  const int tid = threadIdx.x;
  const int wid = tid >> 5, lane = tid & 31;
  const int wm = wid & 3, wn = wid >> 2;
  const int row0 = blockIdx.x * 128;
  const int col0 = blockIdx.y * BN;
  const int NIT = K >> 5;

  const uint32_t a_rel =
      (uint32_t)(wm * 32 + (lane & 15)) * 80u + (uint32_t)(lane >> 4) * 16u;
  const uint32_t b_rel = 20480u +
      (uint32_t)(wn * (BN / 2) + (lane & 7) + ((lane >> 4) << 3)) * 80u +
      (uint32_t)((lane >> 3) & 1) * 16u;

  float c[2][NA][4] = {};

  auto load_stage = [&](int s, int k0) {
    uint32_t sb = smu + (uint32_t)s * ST;
    int r = tid >> 2, q = tid & 3;
#pragma unroll
    for (int p = 0; p < 2; ++p) {
      int rr = r + p * 64;
      int grow = row0 + rr; if (grow >= N) grow = N - 1;
      cp16(sb + rr * 80 + q * 16, Ah + (size_t)grow * K + k0 + q * 8);
      cp16(sb + 10240 + rr * 80 + q * 16, Al + (size_t)grow * K + k0 + q * 8);
    }
#pragma unroll
    for (int p = 0; p < BN / 64; ++p) {
      int rr = r + p * 64;
      int gc = col0 + rr;
      cp16(sb + 20480 + rr * 80 + q * 16, Bh + (size_t)gc * K + k0 + q * 8);
      cp16(sb + 20480 + SB + rr * 80 + q * 16, Bl + (size_t)gc * K + k0 + q * 8);
    }
  };

  load_stage(0, 0);
  cp_commit();
  for (int it = 0; it < NIT; ++it) {
    if (it + 1 < NIT) {
      load_stage((it + 1) & 1, (it + 1) * 32);
      cp_commit();
      cp_wait<1>();
    } else {
      cp_wait<0>();
    }
    __syncthreads();
    uint32_t sbu = smu + (uint32_t)(it & 1) * ST;
#pragma unroll
    for (int ka = 0; ka < 2; ++ka) {
      uint32_t ah[2][4], al[2][4];
#pragma unroll
      for (int ma = 0; ma < 2; ++ma) {
        uint32_t base = sbu + a_rel + (uint32_t)ma * 1280u + (uint32_t)ka * 32u;
        LDM4(ah[ma], base);
        LDM4(al[ma], base + 10240u);
      }
#pragma unroll
      for (int p = 0; p < NP; ++p) {
        uint32_t base = sbu + b_rel + (uint32_t)p * (16u * 80u) + (uint32_t)ka * 32u;
        uint32_t rb[4], rl[4];
        LDM4(rb, base);
        LDM4(rl, base + (uint32_t)SB);
#pragma unroll
        for (int ma = 0; ma < 2; ++ma) {
          MMA_BF16(c[ma][2 * p],     ah[ma], rb[0], rb[1]);
          MMA_BF16(c[ma][2 * p],     al[ma], rb[0], rb[1]);
          MMA_BF16(c[ma][2 * p],     ah[ma], rl[0], rl[1]);
          MMA_BF16(c[ma][2 * p + 1], ah[ma], rb[2], rb[3]);
          MMA_BF16(c[ma][2 * p + 1], al[ma], rb[2], rb[3]);
          MMA_BF16(c[ma][2 * p + 1], ah[ma], rl[2], rl[3]);
        }
      }
    }
    __syncthreads();
  }

  const int gq = lane >> 2, tq = lane & 3;
#pragma unroll
  for (int ma = 0; ma < 2; ++ma) {
    int row = row0 + wm * 32 + ma * 16 + gq;
#pragma unroll
    for (int na = 0; na < NA; ++na) {
      int col = col0 + wn * (BN / 2) + na * 8 + tq * 2;
      if (row < N)
        *(float2*)(C + (size_t)row * Fout + col) =
            make_float2(c[ma][na][0], c[ma][na][1]);
      if (row + 8 < N)
        *(float2*)(C + (size_t)(row + 8) * Fout + col) =
            make_float2(c[ma][na][2], c[ma][na][3]);
    }
  }
}

// -------------- CSR gather + fused bias/lrelu/bf16-split --------------------
template<int F>
__global__ void gather_split_kernel(const float* __restrict__ tmp,
                                    const float* __restrict__ bias,
                                    __nv_bfloat16* __restrict__ oh,
                                    __nv_bfloat16* __restrict__ ol, int n) {
  int w = (blockIdx.x * blockDim.x + threadIdx.x) >> 5;
  int lane = threadIdx.x & 31;
  if (w >= n) return;
  int beg = g_off[w], end = g_off[w + 1];
  float dr = g_dinv[w];
  constexpr int NV = F / 128;
  float4 acc[NV];
  const float4* self = (const float4*)(tmp + (size_t)w * F);
#pragma unroll
  for (int v = 0; v < NV; ++v) {
    float4 x = self[lane + 32 * v];
    acc[v] = make_float4(x.x * dr, x.y * dr, x.z * dr, x.w * dr);
  }
  for (int e0 = beg; e0 < end; e0 += 32) {
    int ne = min(32, end - e0);
    int s = 0; float ww = 0.f;
    if (lane < ne) { s = g_csr_src[e0 + lane]; ww = g_csr_w[e0 + lane]; }
    for (int j = 0; j < ne; ++j) {
      int sj = __shfl_sync(0xffffffffu, s, j);
      float wj = __shfl_sync(0xffffffffu, ww, j);
      const float4* sr = (const float4*)(tmp + (size_t)sj * F);
#pragma unroll
      for (int v = 0; v < NV; ++v) {
        float4 x = sr[lane + 32 * v];
        acc[v].x += wj * x.x; acc[v].y += wj * x.y;
        acc[v].z += wj * x.z; acc[v].w += wj * x.w;
      }
    }
  }
  uint32_t* ph = (uint32_t*)(oh + (size_t)w * F);
  uint32_t* pl = (uint32_t*)(ol + (size_t)w * F);
#pragma unroll
  for (int v = 0; v < NV; ++v) {
    int cb = lane + 32 * v;
    float4 b = *(const float4*)(bias + 4 * cb);
    float4 z = make_float4(acc[v].x * dr + b.x, acc[v].y * dr + b.y,
                           acc[v].z * dr + b.z, acc[v].w * dr + b.w);
    z.x = z.x > 0.f ? z.x : 0.01f * z.x;
    z.y = z.y > 0.f ? z.y : 0.01f * z.y;
    z.z = z.z > 0.f ? z.z : 0.01f * z.z;
    z.w = z.w > 0.f ? z.w : 0.01f * z.w;
    __nv_bfloat16 hx = __float2bfloat16(z.x), hy = __float2bfloat16(z.y);
    __nv_bfloat16 hz = __float2bfloat16(z.z), hw = __float2bfloat16(z.w);
    ph[2 * cb + 0] = pack_bf2(hx, hy);
    ph[2 * cb + 1] = pack_bf2(hz, hw);
    pl[2 * cb + 0] = pack_bf2(__float2bfloat16(z.x - __bfloat162float(hx)),
                              __float2bfloat16(z.y - __bfloat162float(hy)));
    pl[2 * cb + 1] = pack_bf2(__float2bfloat16(z.z - __bfloat162float(hz)),
                              __float2bfloat16(z.w - __bfloat162float(hw)));
  }
}

// ------------------- dropout (JAX threefry) -------------------------
#define TF_ROUND(x0, x1, r)                         \
  { x0 += x1; x1 = (x1 << (r)) | (x1 >> (32 - (r))); x1 ^= x0; }

__device__ __forceinline__ uint32_t threefry_bits(uint32_t idx) {
  const uint32_t k0 = 0u, k1 = 42u;
  const uint32_t k2 = 0x1BD11BDAu ^ k0 ^ k1;
  uint32_t x0 = 0u, x1 = idx;
  x0 += k0; x1 += k1;
  TF_ROUND(x0, x1, 13) TF_ROUND(x0, x1, 15) TF_ROUND(x0, x1, 26) TF_ROUND(x0, x1, 6)
  x0 += k1; x1 += k2 + 1u;
  TF_ROUND(x0, x1, 17) TF_ROUND(x0, x1, 29) TF_ROUND(x0, x1, 16) TF_ROUND(x0, x1, 24)
  x0 += k2; x1 += k0 + 2u;
  TF_ROUND(x0, x1, 13) TF_ROUND(x0, x1, 15) TF_ROUND(x0, x1, 26) TF_ROUND(x0, x1, 6)
  x0 += k0; x1 += k1 + 3u;
  TF_ROUND(x0, x1, 17) TF_ROUND(x0, x1, 29) TF_ROUND(x0, x1, 16) TF_ROUND(x0, x1, 24)
  x0 += k1; x1 += k2 + 4u;
  TF_ROUND(x0, x1, 13) TF_ROUND(x0, x1, 15) TF_ROUND(x0, x1, 26) TF_ROUND(x0, x1, 6)
  x0 += k2; x1 += k0 + 5u;
  return x0 ^ x1;
}

// L4 gather fused with bias4 + lrelu + dropout + dense 64->10.
__global__ void gather_final_kernel(const float* __restrict__ tmp,
                                    const float* __restrict__ b4,
                                    const float* __restrict__ W5,
                                    const float* __restrict__ b5,
                                    float* __restrict__ out, int n) {
  __shared__ float w5s[640];
  __shared__ float b5s[16];
  for (int i = threadIdx.x; i < 640; i += blockDim.x) w5s[i] = W5[i];
  if (threadIdx.x < 10) b5s[threadIdx.x] = b5[threadIdx.x];
  __syncthreads();

  int w = (blockIdx.x * blockDim.x + threadIdx.x) >> 5;
  int lane = threadIdx.x & 31;
  if (w >= n) return;
  int beg = g_off[w], end = g_off[w + 1];
  float dr = g_dinv[w];
  float2 acc;
  {
    float2 x = ((const float2*)(tmp + (size_t)w * 64))[lane];
    acc = make_float2(x.x * dr, x.y * dr);
  }
  for (int e0 = beg; e0 < end; e0 += 32) {
    int ne = min(32, end - e0);
    int s = 0; float ww = 0.f;
    if (lane < ne) { s = g_csr_src[e0 + lane]; ww = g_csr_w[e0 + lane]; }
    for (int j = 0; j < ne; ++j) {
      int sj = __shfl_sync(0xffffffffu, s, j);
      float wj = __shfl_sync(0xffffffffu, ww, j);
      float2 x = ((const float2*)(tmp + (size_t)sj * 64))[lane];
      acc.x += wj * x.x; acc.y += wj * x.y;
    }
  }
  int f0 = 2 * lane, f1 = 2 * lane + 1;
  float v0 = acc.x * dr + b4[f0];
  v0 = (v0 > 0.f) ? v0 : 0.01f * v0;
  float v1 = acc.y * dr + b4[f1];
  v1 = (v1 > 0.f) ? v1 : 0.01f * v1;
  uint32_t bits0 = threefry_bits((uint32_t)(w * 64 + f0));
  uint32_t bits1 = threefry_bits((uint32_t)(w * 64 + f1));
  v0 = (bits0 & 0x80000000u) ? 0.f : v0 * 2.f;
  v1 = (bits1 & 0x80000000u) ? 0.f : v1 * 2.f;
#pragma unroll
  for (int j = 0; j < 10; ++j) {
    float p = v0 * w5s[f0 * 10 + j] + v1 * w5s[f1 * 10 + j];
#pragma unroll
    for (int off = 16; off; off >>= 1)
      p += __shfl_xor_sync(0xffffffffu, p, off);
    if (lane == 0) out[w * 10 + j] = p + b5s[j];
  }
}

// ------------------------------ launch -------------------------------------
extern "C" void kernel_launch(void* const* d_in, const int* in_sizes, int n_in,
                              void* d_out, int out_size) {
  const float* x = (const float*)d_in[0];
  const int* ei = (const int*)d_in[1];   // int32
  const float* W1 = (const float*)d_in[2];
  const float* b1 = (const float*)d_in[3];
  const float* W2 = (const float*)d_in[4];
  const float* b2 = (const float*)d_in[5];
  const float* W3 = (const float*)d_in[6];
  const float* b3 = (const float*)d_in[7];
  const float* W4 = (const float*)d_in[8];
  const float* b4 = (const float*)d_in[9];
  const float* W5 = (const float*)d_in[10];
  const float* b5 = (const float*)d_in[11];
  const int N = in_sizes[0] / 256;
  const int E = in_sizes[1] / 2;
  const int* src = ei;
  const int* dstp = ei + E;

  float* tmp = nullptr;
  __nv_bfloat16 *ah = nullptr, *al = nullptr, *wh = nullptr, *wl = nullptr;
  cudaGetSymbolAddress((void**)&tmp, g_tmp);
  cudaGetSymbolAddress((void**)&ah, g_ah);
  cudaGetSymbolAddress((void**)&al, g_al);
  cudaGetSymbolAddress((void**)&wh, g_wh);
  cudaGetSymbolAddress((void**)&wl, g_wl);

  constexpr int SM_128 = 2 * (20480 + 2 * 128 * 80);  // 81920
  constexpr int SM_64  = 2 * (20480 + 2 * 64 * 80);   // 61440
  cudaFuncSetAttribute(gemm_bf16_kernel<128>,
                       cudaFuncAttributeMaxDynamicSharedMemorySize, SM_128);
  cudaFuncSetAttribute(gemm_bf16_kernel<64>,
                       cudaFuncAttributeMaxDynamicSharedMemorySize, SM_64);

  // Side stream + events (created once on the first, non-captured call).
  static cudaStream_t s2 = nullptr;
  static cudaEvent_t ev_fork = nullptr, ev_w = nullptr, ev_join = nullptr;
  if (s2 == nullptr) {
    cudaStreamCreateWithFlags(&s2, cudaStreamNonBlocking);
    cudaEventCreateWithFlags(&ev_fork, cudaEventDisableTiming);
    cudaEventCreateWithFlags(&ev_w, cudaEventDisableTiming);
    cudaEventCreateWithFlags(&ev_join, cudaEventDisableTiming);
  }

  // ---- fork: W-split + CSR build on s2 ----
  cudaEventRecord(ev_fork, 0);
  cudaStreamWaitEvent(s2, ev_fork, 0);
  split_wt_all_kernel<<<(172032 + 255) / 256, 256, 0, s2>>>(W1, W2, W3, W4, wh, wl);
  cudaEventRecord(ev_w, s2);           // L1 GEMM needs W planes
  deg_init_kernel<<<(N + 255) / 256, 256, 0, s2>>>(N);
  deg_count_kernel<<<(E + 255) / 256, 256, 0, s2>>>(dstp, E);
  int nblk = (N + SCAN_BLK - 1) / SCAN_BLK;
  scan1_kernel<<<nblk, SCAN_BLK, 0, s2>>>(N);
  scan2_kernel<<<1, 64, 0, s2>>>(nblk);
  scan3_kernel<<<(N + 256) / 256, 256, 0, s2>>>(N, E);
  fill_kernel<<<(E + 255) / 256, 256, 0, s2>>>(src, dstp, E);
  cudaEventRecord(ev_join, s2);

  // ---- main stream: x split + L1 GEMM ----
  split_x_kernel<<<(N * 256 + 255) / 256, 256>>>(x, ah, al, N * 256);

  const int MB = (N + 127) / 128;       // 391
  const int GW = (N * 32 + 255) / 256;  // warp per row

  cudaStreamWaitEvent(0, ev_w, 0);      // W planes ready
  gemm_bf16_kernel<128><<<dim3(MB, 2), 256, SM_128>>>(
      ah, al, wh, wl, tmp, N, 256, 256);

  cudaStreamWaitEvent(0, ev_join, 0);   // gathers need the CSR
  gather_split_kernel<256><<<GW, 256>>>(tmp, b1, ah, al, N);

  // L2: 256->256
  gemm_bf16_kernel<128><<<dim3(MB, 2), 256, SM_128>>>(
      ah, al, wh + 65536, wl + 65536, tmp, N, 256, 256);
  gather_split_kernel<256><<<GW, 256>>>(tmp, b2, ah, al, N);

  // L3: 256->128
  gemm_bf16_kernel<128><<<dim3(MB, 1), 256, SM_128>>>(
      ah, al, wh + 131072, wl + 131072, tmp, N, 256, 128);
  gather_split_kernel<128><<<GW, 256>>>(tmp, b3, ah, al, N);

  // L4: 128->64, gather fused with final epilogue
  gemm_bf16_kernel<64><<<dim3(MB, 1), 256, SM_64>>>(
      ah, al, wh + 163840, wl + 163840, tmp, N, 128, 64);
  gather_final_kernel<<<GW, 256>>>(tmp, b4, W5, b5, (float*)d_out, N);
}